// round 17
// baseline (speedup 1.0000x reference)
#include <cuda_runtime.h>
#include <cuda_bf16.h>
#include <cstdint>

// ConvPooler — per-token dot(h[b,s,:], w) + bias scattered into
// out[b, gene_pos[b,s]] over a [B, 60000] zeroed buffer; pad id 60000 dropped.
// B=32, S=2048, D=512, FULL_SEQ_LEN=60000. gene_pos is int32.
//
// Graph with parallel branches:
//   side stream: cudaMemsetAsync(out, 0)  — fill engine, no SM competition,
//                overlapped with the conv (which only touches g_vals scratch)
//   main stream: conv -> dense g_vals (pure HBM read stream, R2 shape)
//   join:        scatter kernel (g_vals + gene_pos are L2-hot)

#define B_DIM 32
#define S_DIM 2048
#define D_DIM 512
#define FULL_SEQ 60000
#define NTOK (B_DIM * S_DIM)   // 65536 tokens

// Dense per-token conv results (bias added). 256 KB static scratch.
__device__ float g_vals[NTOK];

// ---------------------------------------------------------------------------
// Conv kernel: one warp per token (R2-proven 24.8us shape), dense output.
// ---------------------------------------------------------------------------
__global__ __launch_bounds__(256, 8)
void conv_dense_kernel(const float4* __restrict__ h,   // [B*S, D/4]
                       const float4* __restrict__ w,   // [D/4]
                       const float* __restrict__ bias) // [1]
{
    const int warp_id = (blockIdx.x * blockDim.x + threadIdx.x) >> 5;
    const int lane    = threadIdx.x & 31;
    if (warp_id >= NTOK) return;

    const float4* hrow = h + (size_t)warp_id * (D_DIM / 4);

    float acc = 0.f;
#pragma unroll
    for (int j = 0; j < 4; ++j) {
        const int idx = lane + 32 * j;
        float4 hv = hrow[idx];
        float4 wv = __ldg(&w[idx]);   // broadcast; L1-resident after first touch
        acc = fmaf(hv.x, wv.x, acc);
        acc = fmaf(hv.y, wv.y, acc);
        acc = fmaf(hv.z, wv.z, acc);
        acc = fmaf(hv.w, wv.w, acc);
    }

#pragma unroll
    for (int off = 16; off > 0; off >>= 1)
        acc += __shfl_xor_sync(0xFFFFFFFFu, acc, off);

    if (lane == 0)
        g_vals[warp_id] = acc + bias[0];
}

// ---------------------------------------------------------------------------
// Scatter kernel (join): one thread per token; all reads L2-resident.
// ---------------------------------------------------------------------------
__global__ void scatter_kernel(const int* __restrict__ gene_pos,  // [B*S]
                               float* __restrict__ out) {         // [B, FULL_SEQ]
    const int tok = blockIdx.x * blockDim.x + threadIdx.x;
    if (tok >= NTOK) return;
    const int gp = gene_pos[tok];
    if (gp >= 0 && gp < FULL_SEQ) {
        const int row = tok >> 11;          // tok / S_DIM
        out[(size_t)row * FULL_SEQ + (size_t)gp] = g_vals[tok];
    }
}

// ---------------------------------------------------------------------------
// Launch — memset forked onto a side stream, concurrent with conv.
// Inputs mapped by element count: h=33554432, gene_pos=65536, w=512, b=1.
// ---------------------------------------------------------------------------
extern "C" void kernel_launch(void* const* d_in, const int* in_sizes, int n_in,
                              void* d_out, int out_size) {
    const void* h_p = nullptr;
    const void* gp_p = nullptr;
    const void* w_p = nullptr;
    const void* b_p = nullptr;
    for (int i = 0; i < n_in; ++i) {
        switch (in_sizes[i]) {
            case B_DIM * S_DIM * D_DIM: h_p  = d_in[i]; break;  // 33,554,432
            case B_DIM * S_DIM:         gp_p = d_in[i]; break;  // 65,536
            case D_DIM:                 w_p  = d_in[i]; break;  // 512
            case 1:                     b_p  = d_in[i]; break;
            default: break;
        }
    }

    // Host-side objects only (no device memory).
    static cudaStream_t s_side = nullptr;
    static cudaEvent_t  s_fork = nullptr, s_join = nullptr;
    static bool s_tried = false;
    if (!s_tried) {
        s_tried = true;
        if (cudaStreamCreateWithFlags(&s_side, cudaStreamNonBlocking) != cudaSuccess)
            s_side = nullptr;
        if (s_side) {
            if (cudaEventCreateWithFlags(&s_fork, cudaEventDisableTiming) != cudaSuccess ||
                cudaEventCreateWithFlags(&s_join, cudaEventDisableTiming) != cudaSuccess)
                s_side = nullptr;   // sequential fallback
        }
    }

    const size_t out_bytes = (size_t)out_size * sizeof(float);

    if (s_side) {
        // Fork: side stream depends on capture-stream start.
        cudaEventRecord(s_fork, 0);
        cudaStreamWaitEvent(s_side, s_fork, 0);

        // Branch B: memset on the side stream — overlapped with conv.
        cudaMemsetAsync(d_out, 0, out_bytes, s_side);
        cudaEventRecord(s_join, s_side);

        // Branch A: conv -> dense scratch (no touch of out: no race).
        conv_dense_kernel<<<(NTOK * 32) / 256, 256>>>(
            (const float4*)h_p, (const float4*)w_p, (const float*)b_p);

        // Join, then scatter.
        cudaStreamWaitEvent(0, s_join, 0);
        scatter_kernel<<<NTOK / 256, 256>>>((const int*)gp_p, (float*)d_out);
    } else {
        // Sequential fallback (still correct).
        cudaMemsetAsync(d_out, 0, out_bytes, 0);
        conv_dense_kernel<<<(NTOK * 32) / 256, 256>>>(
            (const float4*)h_p, (const float4*)w_p, (const float*)b_p);
        scatter_kernel<<<NTOK / 256, 256>>>((const int*)gp_p, (float*)d_out);
    }
}